// round 5
// baseline (speedup 1.0000x reference)
#include <cuda_runtime.h>
#include <cuda_bf16.h>

// Problem constants (match reference)
#define B_SZ       128
#define S_SZ       4096
#define TOK        64          // token_dim
#define EFF        60          // token_dim - 4
#define NF         20          // num features
#define H0         256
#define H1         128
#define H2         64
#define OUT        3
#define NT         1024        // threads per block (32 warps -> 2x in-flight loads)

// ---------------------------------------------------------------------------
// One block per batch: stream-reduce the whole batch (1 MB), then run the
// per-batch MLP in the same block. No cross-block communication.
// grid = 128 blocks (single wave on 148 SMs), 1024 threads.
// ---------------------------------------------------------------------------
__global__ __launch_bounds__(NT, 1)
void fused_kernel(const float* __restrict__ x,
                  const float* __restrict__ w_ext, const float* __restrict__ b_ext,
                  const float* __restrict__ w0, const float* __restrict__ b0,
                  const float* __restrict__ w1, const float* __restrict__ b1,
                  const float* __restrict__ w2, const float* __restrict__ b2,
                  const float* __restrict__ w3, const float* __restrict__ b3,
                  float* __restrict__ out) {
    const int b = blockIdx.x;             // batch
    const int t = threadIdx.x;            // 0..1023

    __shared__ float4 sm[NT];             // 16 KB reduction buffer
    __shared__ float xm[TOK];
    __shared__ float feats[NF];
    __shared__ float a0[H0];
    __shared__ float a1[H1];
    __shared__ float a2[H2];

    // ---------------- Phase 1: streaming column sum over the whole batch ---
    {
        const float4* __restrict__ p = (const float4*)(x + (size_t)b * S_SZ * TOK);
        // 4096 tokens * 16 float4/token = 65536 float4; 64 per thread.
        // Stride NT=1024 is a multiple of 16, so each thread stays on one
        // float4 column-group (t & 15) -> conflict-free accumulation.
        float4 acc = make_float4(0.f, 0.f, 0.f, 0.f);
        #pragma unroll 8
        for (int i = t; i < S_SZ * (TOK / 4); i += NT) {
            float4 v = __ldcs(&p[i]);     // streaming: x touched exactly once
            acc.x += v.x; acc.y += v.y; acc.z += v.z; acc.w += v.w;
        }
        sm[t] = acc;
        __syncthreads();

        // 16 column groups; 64 contributing threads per group.
        if (t < 16) {
            float4 s0 = make_float4(0.f, 0.f, 0.f, 0.f);
            float4 s1 = make_float4(0.f, 0.f, 0.f, 0.f);
            #pragma unroll
            for (int k = 0; k < 64; k += 2) {
                float4 v0 = sm[t + (k + 0) * 16];
                float4 v1 = sm[t + (k + 1) * 16];
                s0.x += v0.x; s0.y += v0.y; s0.z += v0.z; s0.w += v0.w;
                s1.x += v1.x; s1.y += v1.y; s1.z += v1.z; s1.w += v1.w;
            }
            const float inv = 1.0f / (float)S_SZ;
            xm[t * 4 + 0] = (s0.x + s1.x) * inv;
            xm[t * 4 + 1] = (s0.y + s1.y) * inv;
            xm[t * 4 + 2] = (s0.z + s1.z) * inv;
            xm[t * 4 + 3] = (s0.w + s1.w) * inv;
        }
        __syncthreads();
    }

    // ---------------- Phase 2: per-batch MLP -------------------------------
    // Extractor: 20 outputs, dot over EFF=60; 4 accumulators break the chain
    if (t < NF) {
        const float* __restrict__ w = w_ext + t * EFF;
        float s0 = b_ext[t], s1 = 0.f, s2 = 0.f, s3 = 0.f;
        #pragma unroll
        for (int k = 0; k < EFF; k += 4) {
            s0 = fmaf(xm[k + 0], w[k + 0], s0);
            s1 = fmaf(xm[k + 1], w[k + 1], s1);
            s2 = fmaf(xm[k + 2], w[k + 2], s2);
            s3 = fmaf(xm[k + 3], w[k + 3], s3);
        }
        feats[t] = (s0 + s1) + (s2 + s3);
    }
    __syncthreads();

    // Layer 0: 20 -> 256 + ReLU (one neuron per thread, threads 0..255)
    if (t < H0) {
        const float* __restrict__ w = w0 + t * NF;
        float s0 = b0[t], s1 = 0.f;
        #pragma unroll
        for (int k = 0; k < NF; k += 2) {
            s0 = fmaf(feats[k + 0], w[k + 0], s0);
            s1 = fmaf(feats[k + 1], w[k + 1], s1);
        }
        a0[t] = fmaxf(s0 + s1, 0.f);
    }
    __syncthreads();

    // Layer 1: 256 -> 128 + ReLU. Eight threads per neuron (j = t>>3),
    // each handles 32 elements (8 float4), then 3-step shfl reduction.
    {
        const int j = t >> 3;             // neuron 0..127
        const int o = t & 7;
        const float4* __restrict__ w = (const float4*)(w1 + j * H0) + o * 8;
        const float4* __restrict__ hv = (const float4*)a0 + o * 8;
        float s0 = 0.f, s1 = 0.f, s2 = 0.f, s3 = 0.f;
        #pragma unroll
        for (int k = 0; k < 8; k++) {
            float4 wv = w[k];
            float4 av = hv[k];
            s0 = fmaf(av.x, wv.x, s0);
            s1 = fmaf(av.y, wv.y, s1);
            s2 = fmaf(av.z, wv.z, s2);
            s3 = fmaf(av.w, wv.w, s3);
        }
        float s = (s0 + s1) + (s2 + s3);
        s += __shfl_xor_sync(0xFFFFFFFF, s, 1);
        s += __shfl_xor_sync(0xFFFFFFFF, s, 2);
        s += __shfl_xor_sync(0xFFFFFFFF, s, 4);
        if (o == 0) a1[j] = fmaxf(s + b1[j], 0.f);
    }
    __syncthreads();

    // Layer 2: 128 -> 64 + ReLU. Sixteen threads per neuron (j = t>>4),
    // each handles 8 elements (2 float4), then 4-step shfl reduction.
    {
        const int j = t >> 4;             // neuron 0..63
        const int o = t & 15;
        const float4* __restrict__ w = (const float4*)(w2 + j * H1) + o * 2;
        const float4* __restrict__ hv = (const float4*)a1 + o * 2;
        float s0 = 0.f, s1 = 0.f, s2 = 0.f, s3 = 0.f;
        #pragma unroll
        for (int k = 0; k < 2; k++) {
            float4 wv = w[k];
            float4 av = hv[k];
            s0 = fmaf(av.x, wv.x, s0);
            s1 = fmaf(av.y, wv.y, s1);
            s2 = fmaf(av.z, wv.z, s2);
            s3 = fmaf(av.w, wv.w, s3);
        }
        float s = (s0 + s1) + (s2 + s3);
        s += __shfl_xor_sync(0xFFFFFFFF, s, 1);
        s += __shfl_xor_sync(0xFFFFFFFF, s, 2);
        s += __shfl_xor_sync(0xFFFFFFFF, s, 4);
        s += __shfl_xor_sync(0xFFFFFFFF, s, 8);
        if (o == 0) a2[j] = fmaxf(s + b2[j], 0.f);
    }
    __syncthreads();

    // Layer 3: 64 -> 3 (no activation)
    if (t < OUT) {
        const float4* __restrict__ w = (const float4*)(w3 + t * H2);
        const float4* __restrict__ hv = (const float4*)a2;
        float s0 = b3[t], s1 = 0.f, s2 = 0.f, s3 = 0.f;
        #pragma unroll
        for (int k = 0; k < H2 / 4; k++) {
            float4 wv = w[k];
            float4 av = hv[k];
            s0 = fmaf(av.x, wv.x, s0);
            s1 = fmaf(av.y, wv.y, s1);
            s2 = fmaf(av.z, wv.z, s2);
            s3 = fmaf(av.w, wv.w, s3);
        }
        out[b * OUT + t] = (s0 + s1) + (s2 + s3);
    }
}

extern "C" void kernel_launch(void* const* d_in, const int* in_sizes, int n_in,
                              void* d_out, int out_size) {
    const float* x     = (const float*)d_in[0];
    const float* w_ext = (const float*)d_in[1];
    const float* b_ext = (const float*)d_in[2];
    const float* w0    = (const float*)d_in[3];
    const float* b0    = (const float*)d_in[4];
    const float* w1    = (const float*)d_in[5];
    const float* b1    = (const float*)d_in[6];
    const float* w2    = (const float*)d_in[7];
    const float* b2    = (const float*)d_in[8];
    const float* w3    = (const float*)d_in[9];
    const float* b3    = (const float*)d_in[10];
    float* out = (float*)d_out;

    fused_kernel<<<B_SZ, NT>>>(x, w_ext, b_ext, w0, b0, w1, b1,
                               w2, b2, w3, b3, out);
}

// round 6
// speedup vs baseline: 1.1865x; 1.1865x over previous
#include <cuda_runtime.h>
#include <cuda_bf16.h>

// Problem constants (match reference)
#define B_SZ       128
#define S_SZ       4096
#define TOK        64          // token_dim
#define EFF        60          // token_dim - 4
#define NF         20          // num features
#define H0         256
#define H1         128
#define H2         64
#define OUT        3
#define NT         512         // threads per block (16 warps)

__device__ __forceinline__ void l2_prefetch(const void* p) {
    asm volatile("prefetch.global.L2 [%0];" :: "l"(p));
}

// ---------------------------------------------------------------------------
// One block per batch: stream-reduce the whole batch (1 MB), then run the
// per-batch MLP in the same block with warp-per-neuron coalesced weight reads.
// grid = 128 blocks, 512 threads.
// ---------------------------------------------------------------------------
__global__ __launch_bounds__(NT, 1)
void fused_kernel(const float* __restrict__ x,
                  const float* __restrict__ w_ext, const float* __restrict__ b_ext,
                  const float* __restrict__ w0, const float* __restrict__ b0,
                  const float* __restrict__ w1, const float* __restrict__ b1,
                  const float* __restrict__ w2, const float* __restrict__ b2,
                  const float* __restrict__ w3, const float* __restrict__ b3,
                  float* __restrict__ out) {
    const int b = blockIdx.x;             // batch
    const int t = threadIdx.x;            // 0..511
    const int w = t >> 5;                 // warp 0..15
    const int lane = t & 31;

    __shared__ float4 sm[NT];             // 8 KB reduction buffer
    __shared__ float xm[TOK];
    __shared__ float feats[NF];
    __shared__ float a0[H0];
    __shared__ float a1[H1];
    __shared__ float a2[H2];

    // ---------------- Prefetch weight slices into L2 (hides under stream) --
    // w1: 1024 lines -> 8/block; w2: 256 lines -> 2/block; w0: 160 lines;
    // w_ext: 38 lines. Each block touches a disjoint slice; full coverage.
    if (t < 8)                l2_prefetch(w1 + (b * 8 + t) * 32);
    else if (t < 10)          l2_prefetch(w2 + (b * 2 + (t - 8)) * 32);
    else if (t == 10 && b < 160) l2_prefetch(w0 + b * 32);
    else if (t == 11 && b < 38)  l2_prefetch(w_ext + b * 32);

    // ---------------- Phase 1: streaming column sum over the whole batch ---
    {
        const float4* __restrict__ p = (const float4*)(x + (size_t)b * S_SZ * TOK);
        // 65536 float4; 128 per thread. Stride 512 is a multiple of 16 ->
        // each thread stays on one float4 column-group (t & 15).
        float4 acc = make_float4(0.f, 0.f, 0.f, 0.f);
        #pragma unroll 8
        for (int i = t; i < S_SZ * (TOK / 4); i += NT) {
            float4 v = __ldcs(&p[i]);     // streaming: x touched exactly once
            acc.x += v.x; acc.y += v.y; acc.z += v.z; acc.w += v.w;
        }
        sm[t] = acc;
        __syncthreads();

        // 16 column groups; 32 contributing threads per group.
        if (t < 16) {
            float4 s = make_float4(0.f, 0.f, 0.f, 0.f);
            #pragma unroll
            for (int k = 0; k < 32; k++) {
                float4 v = sm[t + k * 16];
                s.x += v.x; s.y += v.y; s.z += v.z; s.w += v.w;
            }
            const float inv = 1.0f / (float)S_SZ;
            xm[t * 4 + 0] = s.x * inv;
            xm[t * 4 + 1] = s.y * inv;
            xm[t * 4 + 2] = s.z * inv;
            xm[t * 4 + 3] = s.w * inv;
        }
        __syncthreads();
    }

    // ---------------- Phase 2: per-batch MLP, warp-per-neuron --------------

    // Extractor: 20 neurons, 60-dot. Warp w does neuron w (and 16+w for w<4).
    // Lanes 0..14 each read one float4 of the row -> coalesced 240B.
    {
        #pragma unroll
        for (int r = 0; r < 2; r++) {
            const int j = w + r * 16;
            if (j < NF) {
                float s = 0.f;
                if (lane < 15) {
                    const float4 wv = ((const float4*)(w_ext + j * EFF))[lane];
                    const float4 av = ((const float4*)xm)[lane];
                    s = fmaf(av.x, wv.x, fmaf(av.y, wv.y,
                        fmaf(av.z, wv.z, av.w * wv.w)));
                }
                s += __shfl_xor_sync(0xFFFFFFFF, s, 1);
                s += __shfl_xor_sync(0xFFFFFFFF, s, 2);
                s += __shfl_xor_sync(0xFFFFFFFF, s, 4);
                s += __shfl_xor_sync(0xFFFFFFFF, s, 8);
                s += __shfl_xor_sync(0xFFFFFFFF, s, 16);
                if (lane == 0) feats[j] = s + b_ext[j];
            }
        }
    }
    __syncthreads();

    // Layer 0: 20 -> 256 + ReLU. One neuron per thread (t < 256).
    // w0 is only 20 KB; short dot, keep it simple.
    if (t < H0) {
        const float* __restrict__ wp = w0 + t * NF;
        float s0 = b0[t], s1 = 0.f;
        #pragma unroll
        for (int k = 0; k < NF; k += 2) {
            s0 = fmaf(feats[k + 0], wp[k + 0], s0);
            s1 = fmaf(feats[k + 1], wp[k + 1], s1);
        }
        a0[t] = fmaxf(s0 + s1, 0.f);
    }
    __syncthreads();

    // Layer 1: 256 -> 128 + ReLU. Warp w does neurons j = w + 16r, r=0..7.
    // Lane reads float4 #lane and #(lane+32) of the row -> 2x coalesced 512B.
    {
        #pragma unroll
        for (int r = 0; r < 8; r++) {
            const int j = w + r * 16;
            const float4* __restrict__ wr = (const float4*)(w1 + j * H0);
            const float4* __restrict__ ar = (const float4*)a0;
            float4 w0v = wr[lane];
            float4 w1v = wr[lane + 32];
            float4 a0v = ar[lane];
            float4 a1v = ar[lane + 32];
            float s0 = fmaf(a0v.x, w0v.x, a0v.y * w0v.y);
            float s1 = fmaf(a0v.z, w0v.z, a0v.w * w0v.w);
            float s2 = fmaf(a1v.x, w1v.x, a1v.y * w1v.y);
            float s3 = fmaf(a1v.z, w1v.z, a1v.w * w1v.w);
            float s = (s0 + s1) + (s2 + s3);
            s += __shfl_xor_sync(0xFFFFFFFF, s, 1);
            s += __shfl_xor_sync(0xFFFFFFFF, s, 2);
            s += __shfl_xor_sync(0xFFFFFFFF, s, 4);
            s += __shfl_xor_sync(0xFFFFFFFF, s, 8);
            s += __shfl_xor_sync(0xFFFFFFFF, s, 16);
            if (lane == 0) a1[j] = fmaxf(s + b1[j], 0.f);
        }
    }
    __syncthreads();

    // Layer 2: 128 -> 64 + ReLU. Warp w does neurons j = w + 16r, r=0..3.
    // Lane reads float4 #lane of the 128-float row -> coalesced 512B.
    {
        #pragma unroll
        for (int r = 0; r < 4; r++) {
            const int j = w + r * 16;
            const float4 wv = ((const float4*)(w2 + j * H1))[lane];
            const float4 av = ((const float4*)a1)[lane];
            float s = fmaf(av.x, wv.x, fmaf(av.y, wv.y,
                      fmaf(av.z, wv.z, av.w * wv.w)));
            s += __shfl_xor_sync(0xFFFFFFFF, s, 1);
            s += __shfl_xor_sync(0xFFFFFFFF, s, 2);
            s += __shfl_xor_sync(0xFFFFFFFF, s, 4);
            s += __shfl_xor_sync(0xFFFFFFFF, s, 8);
            s += __shfl_xor_sync(0xFFFFFFFF, s, 16);
            if (lane == 0) a2[j] = fmaxf(s + b2[j], 0.f);
        }
    }
    __syncthreads();

    // Layer 3: 64 -> 3. Warps 0..2, one neuron each; lanes 0..15 read float4.
    if (w < OUT) {
        const int j = w;
        float s = 0.f;
        if (lane < 16) {
            const float4 wv = ((const float4*)(w3 + j * H2))[lane];
            const float4 av = ((const float4*)a2)[lane];
            s = fmaf(av.x, wv.x, fmaf(av.y, wv.y,
                fmaf(av.z, wv.z, av.w * wv.w)));
        }
        s += __shfl_xor_sync(0xFFFFFFFF, s, 1);
        s += __shfl_xor_sync(0xFFFFFFFF, s, 2);
        s += __shfl_xor_sync(0xFFFFFFFF, s, 4);
        s += __shfl_xor_sync(0xFFFFFFFF, s, 8);
        s += __shfl_xor_sync(0xFFFFFFFF, s, 16);
        if (lane == 0) out[b * OUT + j] = s + b3[j];
    }
}

extern "C" void kernel_launch(void* const* d_in, const int* in_sizes, int n_in,
                              void* d_out, int out_size) {
    const float* x     = (const float*)d_in[0];
    const float* w_ext = (const float*)d_in[1];
    const float* b_ext = (const float*)d_in[2];
    const float* w0    = (const float*)d_in[3];
    const float* b0    = (const float*)d_in[4];
    const float* w1    = (const float*)d_in[5];
    const float* b1    = (const float*)d_in[6];
    const float* w2    = (const float*)d_in[7];
    const float* b2    = (const float*)d_in[8];
    const float* w3    = (const float*)d_in[9];
    const float* b3    = (const float*)d_in[10];
    float* out = (float*)d_out;

    fused_kernel<<<B_SZ, NT>>>(x, w_ext, b_ext, w0, b0, w1, b1,
                               w2, b2, w3, b3, out);
}

// round 7
// speedup vs baseline: 1.2143x; 1.0234x over previous
#include <cuda_runtime.h>
#include <cuda_bf16.h>

// Problem constants (match reference)
#define B_SZ       128
#define S_SZ       4096
#define TOK        64          // token_dim
#define EFF        60          // token_dim - 4
#define NF         20          // num features
#define H0         256
#define H1         128
#define H2         64
#define OUT        3
#define NT         512         // threads per block (16 warps)
#define UNR        16          // batched loads per thread per outer iter

__device__ __forceinline__ void l2_prefetch(const void* p) {
    asm volatile("prefetch.global.L2 [%0];" :: "l"(p));
}

// ---------------------------------------------------------------------------
// One block per batch: stream-reduce the whole batch (1 MB) with 16-deep
// explicitly batched loads (32 KB in flight per SM), then run the per-batch
// MLP with warp-per-neuron coalesced weight reads.
// grid = 128 blocks, 512 threads.
// ---------------------------------------------------------------------------
__global__ __launch_bounds__(NT, 1)
void fused_kernel(const float* __restrict__ x,
                  const float* __restrict__ w_ext, const float* __restrict__ b_ext,
                  const float* __restrict__ w0, const float* __restrict__ b0,
                  const float* __restrict__ w1, const float* __restrict__ b1,
                  const float* __restrict__ w2, const float* __restrict__ b2,
                  const float* __restrict__ w3, const float* __restrict__ b3,
                  float* __restrict__ out) {
    const int b = blockIdx.x;             // batch
    const int t = threadIdx.x;            // 0..511
    const int w = t >> 5;                 // warp 0..15
    const int lane = t & 31;

    __shared__ float4 sm[NT];             // 8 KB reduction buffer
    __shared__ float xm[TOK];
    __shared__ float feats[NF];
    __shared__ float a0[H0];
    __shared__ float a1[H1];
    __shared__ float a2[H2];

    // ---------------- Prefetch weight slices into L2 (hides under stream) --
    if (t < 8)                l2_prefetch(w1 + (b * 8 + t) * 32);
    else if (t < 10)          l2_prefetch(w2 + (b * 2 + (t - 8)) * 32);
    else if (t == 10 && b < 160) l2_prefetch(w0 + b * 32);
    else if (t == 11 && b < 38)  l2_prefetch(w_ext + b * 32);

    // ---------------- Phase 1: streaming column sum over the whole batch ---
    {
        const float4* __restrict__ p =
            (const float4*)(x + (size_t)b * S_SZ * TOK) + t;
        // 65536 float4 total; 128 per thread = 8 outer iters x 16 batched
        // loads. The 16 loads are independent and front-issued -> 16 LDG.128
        // in flight per thread (32 KB/SM at 16 warps).
        float4 acc0 = make_float4(0.f, 0.f, 0.f, 0.f);
        float4 acc1 = make_float4(0.f, 0.f, 0.f, 0.f);
        #pragma unroll 1
        for (int it = 0; it < (S_SZ * (TOK / 4)) / (NT * UNR); it++) {
            float4 v[UNR];
            #pragma unroll
            for (int j = 0; j < UNR; j++)
                v[j] = __ldcs(p + (size_t)(it * UNR + j) * NT);
            #pragma unroll
            for (int j = 0; j < UNR; j += 2) {
                acc0.x += v[j].x;   acc0.y += v[j].y;
                acc0.z += v[j].z;   acc0.w += v[j].w;
                acc1.x += v[j+1].x; acc1.y += v[j+1].y;
                acc1.z += v[j+1].z; acc1.w += v[j+1].w;
            }
        }
        acc0.x += acc1.x; acc0.y += acc1.y; acc0.z += acc1.z; acc0.w += acc1.w;
        sm[t] = acc0;
        __syncthreads();

        // 16 column groups (stride NT multiple of 16 keeps lanes on one
        // float4 column-group); 32 contributing threads per group.
        if (t < 16) {
            float4 s = make_float4(0.f, 0.f, 0.f, 0.f);
            #pragma unroll
            for (int k = 0; k < 32; k++) {
                float4 v = sm[t + k * 16];
                s.x += v.x; s.y += v.y; s.z += v.z; s.w += v.w;
            }
            const float inv = 1.0f / (float)S_SZ;
            xm[t * 4 + 0] = s.x * inv;
            xm[t * 4 + 1] = s.y * inv;
            xm[t * 4 + 2] = s.z * inv;
            xm[t * 4 + 3] = s.w * inv;
        }
        __syncthreads();
    }

    // ---------------- Phase 2: per-batch MLP, warp-per-neuron --------------

    // Extractor: 20 neurons, 60-dot. Warp w does neuron w (and 16+w for w<4).
    {
        #pragma unroll
        for (int r = 0; r < 2; r++) {
            const int j = w + r * 16;
            if (j < NF) {
                float s = 0.f;
                if (lane < 15) {
                    const float4 wv = ((const float4*)(w_ext + j * EFF))[lane];
                    const float4 av = ((const float4*)xm)[lane];
                    s = fmaf(av.x, wv.x, fmaf(av.y, wv.y,
                        fmaf(av.z, wv.z, av.w * wv.w)));
                }
                s += __shfl_xor_sync(0xFFFFFFFF, s, 1);
                s += __shfl_xor_sync(0xFFFFFFFF, s, 2);
                s += __shfl_xor_sync(0xFFFFFFFF, s, 4);
                s += __shfl_xor_sync(0xFFFFFFFF, s, 8);
                s += __shfl_xor_sync(0xFFFFFFFF, s, 16);
                if (lane == 0) feats[j] = s + b_ext[j];
            }
        }
    }
    __syncthreads();

    // Layer 0: 20 -> 256 + ReLU. One neuron per thread (t < 256).
    if (t < H0) {
        const float* __restrict__ wp = w0 + t * NF;
        float s0 = b0[t], s1 = 0.f;
        #pragma unroll
        for (int k = 0; k < NF; k += 2) {
            s0 = fmaf(feats[k + 0], wp[k + 0], s0);
            s1 = fmaf(feats[k + 1], wp[k + 1], s1);
        }
        a0[t] = fmaxf(s0 + s1, 0.f);
    }
    __syncthreads();

    // Layer 1: 256 -> 128 + ReLU. Warp w does neurons j = w + 16r, r=0..7.
    {
        #pragma unroll
        for (int r = 0; r < 8; r++) {
            const int j = w + r * 16;
            const float4* __restrict__ wr = (const float4*)(w1 + j * H0);
            const float4* __restrict__ ar = (const float4*)a0;
            float4 w0v = wr[lane];
            float4 w1v = wr[lane + 32];
            float4 a0v = ar[lane];
            float4 a1v = ar[lane + 32];
            float s0 = fmaf(a0v.x, w0v.x, a0v.y * w0v.y);
            float s1 = fmaf(a0v.z, w0v.z, a0v.w * w0v.w);
            float s2 = fmaf(a1v.x, w1v.x, a1v.y * w1v.y);
            float s3 = fmaf(a1v.z, w1v.z, a1v.w * w1v.w);
            float s = (s0 + s1) + (s2 + s3);
            s += __shfl_xor_sync(0xFFFFFFFF, s, 1);
            s += __shfl_xor_sync(0xFFFFFFFF, s, 2);
            s += __shfl_xor_sync(0xFFFFFFFF, s, 4);
            s += __shfl_xor_sync(0xFFFFFFFF, s, 8);
            s += __shfl_xor_sync(0xFFFFFFFF, s, 16);
            if (lane == 0) a1[j] = fmaxf(s + b1[j], 0.f);
        }
    }
    __syncthreads();

    // Layer 2: 128 -> 64 + ReLU. Warp w does neurons j = w + 16r, r=0..3.
    {
        #pragma unroll
        for (int r = 0; r < 4; r++) {
            const int j = w + r * 16;
            const float4 wv = ((const float4*)(w2 + j * H1))[lane];
            const float4 av = ((const float4*)a1)[lane];
            float s = fmaf(av.x, wv.x, fmaf(av.y, wv.y,
                      fmaf(av.z, wv.z, av.w * wv.w)));
            s += __shfl_xor_sync(0xFFFFFFFF, s, 1);
            s += __shfl_xor_sync(0xFFFFFFFF, s, 2);
            s += __shfl_xor_sync(0xFFFFFFFF, s, 4);
            s += __shfl_xor_sync(0xFFFFFFFF, s, 8);
            s += __shfl_xor_sync(0xFFFFFFFF, s, 16);
            if (lane == 0) a2[j] = fmaxf(s + b2[j], 0.f);
        }
    }
    __syncthreads();

    // Layer 3: 64 -> 3. Warps 0..2, one neuron each; lanes 0..15 read float4.
    if (w < OUT) {
        const int j = w;
        float s = 0.f;
        if (lane < 16) {
            const float4 wv = ((const float4*)(w3 + j * H2))[lane];
            const float4 av = ((const float4*)a2)[lane];
            s = fmaf(av.x, wv.x, fmaf(av.y, wv.y,
                fmaf(av.z, wv.z, av.w * wv.w)));
        }
        s += __shfl_xor_sync(0xFFFFFFFF, s, 1);
        s += __shfl_xor_sync(0xFFFFFFFF, s, 2);
        s += __shfl_xor_sync(0xFFFFFFFF, s, 4);
        s += __shfl_xor_sync(0xFFFFFFFF, s, 8);
        s += __shfl_xor_sync(0xFFFFFFFF, s, 16);
        if (lane == 0) out[b * OUT + j] = s + b3[j];
    }
}

extern "C" void kernel_launch(void* const* d_in, const int* in_sizes, int n_in,
                              void* d_out, int out_size) {
    const float* x     = (const float*)d_in[0];
    const float* w_ext = (const float*)d_in[1];
    const float* b_ext = (const float*)d_in[2];
    const float* w0    = (const float*)d_in[3];
    const float* b0    = (const float*)d_in[4];
    const float* w1    = (const float*)d_in[5];
    const float* b1    = (const float*)d_in[6];
    const float* w2    = (const float*)d_in[7];
    const float* b2    = (const float*)d_in[8];
    const float* w3    = (const float*)d_in[9];
    const float* b3    = (const float*)d_in[10];
    float* out = (float*)d_out;

    fused_kernel<<<B_SZ, NT>>>(x, w_ext, b_ext, w0, b0, w1, b1,
                               w2, b2, w3, b3, out);
}